// round 15
// baseline (speedup 1.0000x reference)
#include <cuda_runtime.h>
#include <cuda_fp16.h>
#include <cstdint>

// Problem constants
#define TSTEPS 500
#define BATCH  128
#define WIN    256
#define NFILT  512
#define NCLS   10
#define MROWS  (TSTEPS * BATCH)   // 64000
#define NBF    (BATCH * NFILT)    // 65536
#define RING   50                 // scan ring slots (steps)
#define GRP    10                 // steps per cp.async commit group
#define SCAN_SMEM (RING * 256 * 4)   // 51200 B (dynamic)

// Scratch (device globals: no runtime allocation allowed).
// g_proj padded by 64 timesteps: scan prefetches up to t+49 past the end.
__device__ __align__(16) float g_proj[(size_t)(TSTEPS + 64) * NBF];     // 148 MB
// A in full mma-fragment layout: [p(2)][rt(4000)][ks(16)][lane(32)] x 8 halves
__device__ __align__(16) __half g_af[(size_t)2 * 4000 * 16 * 32 * 8];   // 65.5 MB
// W in full mma-fragment layout: [nblk(4)][ch(8)] x 8192 halves,
// inner: [p(2)][nt(16)][lane(32)][s(2)][reg(2)][slot(2)]
__device__ __align__(16) __half g_wB[4 * 8 * 8192];                     // 512 KB

// ============================================================================
// helpers
// ============================================================================
__device__ __forceinline__ uint32_t smem_u32(const void* p) {
    uint32_t a;
    asm("{ .reg .u64 t; cvta.to.shared.u64 t, %1; cvt.u32.u64 %0, t; }" : "=r"(a) : "l"(p));
    return a;
}
__device__ __forceinline__ void mma16(float* c, const uint32_t* a, const uint32_t* b) {
    asm volatile(
        "mma.sync.aligned.m16n8k16.row.col.f32.f16.f16.f32 "
        "{%0,%1,%2,%3}, {%4,%5,%6,%7}, {%8,%9}, {%0,%1,%2,%3};"
        : "+f"(c[0]), "+f"(c[1]), "+f"(c[2]), "+f"(c[3])
        : "r"(a[0]), "r"(a[1]), "r"(a[2]), "r"(a[3]), "r"(b[0]), "r"(b[1]));
}
__device__ __forceinline__ void split2h(float x, __half& h0, __half& h1) {
    h0 = __float2half_rn(x);
    h1 = __float2half_rn(x - __half2float(h0));
}

// ============================================================================
// Kernel 0a: split X -> 2 fp16 planes directly in mma-fragment layout.
// Thread = (rt, ks, lane): produces the 16B A-fragment for both planes.
// ============================================================================
__global__ __launch_bounds__(256)
void fsnn_asplit(const float* __restrict__ X) {
    int idx  = blockIdx.x * 256 + threadIdx.x;   // 0 .. 2,048,000-1
    int lane = idx & 31;
    int ks   = (idx >> 5) & 15;
    int rt   = idx >> 9;
    int rl = lane >> 2, g = lane & 3;
    int rlo = rt * 16 + rl, rhi = rlo + 8;
    int k0 = ks * 16 + 2 * g;

    float2 lo_a = *(const float2*)(X + (size_t)rlo * WIN + k0);
    float2 lo_b = *(const float2*)(X + (size_t)rlo * WIN + k0 + 8);
    float2 hi_a = *(const float2*)(X + (size_t)rhi * WIN + k0);
    float2 hi_b = *(const float2*)(X + (size_t)rhi * WIN + k0 + 8);

    __half h[8], l[8];
    split2h(lo_a.x, h[0], l[0]); split2h(lo_a.y, h[1], l[1]);
    split2h(hi_a.x, h[2], l[2]); split2h(hi_a.y, h[3], l[3]);
    split2h(lo_b.x, h[4], l[4]); split2h(lo_b.y, h[5], l[5]);
    split2h(hi_b.x, h[6], l[6]); split2h(hi_b.y, h[7], l[7]);

    size_t o0 = ((((size_t)0 * 4000 + rt) * 16 + ks) * 32 + lane) * 8;
    size_t o1 = ((((size_t)1 * 4000 + rt) * 16 + ks) * 32 + lane) * 8;
    __half2* d0 = (__half2*)(g_af + o0);
    __half2* d1 = (__half2*)(g_af + o1);
#pragma unroll
    for (int j = 0; j < 4; j++) {
        d0[j] = __halves2half2(h[2 * j], h[2 * j + 1]);
        d1[j] = __halves2half2(l[2 * j], l[2 * j + 1]);
    }
}

// ============================================================================
// Kernel 0b: split W -> 2 fp16 planes (fragment layout) + init out with bias
// ============================================================================
__global__ __launch_bounds__(256)
void fsnn_wsplit(const float* __restrict__ Wm, const float* __restrict__ dec_b,
                 float* __restrict__ out) {
    if (blockIdx.x == 0) {
        for (int j = threadIdx.x; j < BATCH * NCLS; j += 256)
            out[j] = dec_b[j % NCLS];
    }
    int i = blockIdx.x * blockDim.x + threadIdx.x;
    if (i >= NFILT * WIN) return;
    int n = i >> 8, k = i & 255;
    __half h, l;
    split2h(Wm[i], h, l);

    int nblk = n >> 7, nn = n & 127, nt = nn >> 3;
    int ch = k >> 5, kk = k & 31;
    int s = kk >> 4, q = kk & 15;
    int reg = q >> 3, kr = q & 7;
    int lane = (nn & 7) * 4 + (kr >> 1);
    int slot = kr & 1;

    size_t chbase = (size_t)(nblk * 8 + ch) * 8192;
    size_t o0 = chbase + ((((size_t)(0 * 16 + nt) * 32 + lane) * 2 + s) * 4) + reg * 2 + slot;
    size_t o1 = chbase + ((((size_t)(1 * 16 + nt) * 32 + lane) * 2 + s) * 4) + reg * 2 + slot;
    g_wB[o0] = h;
    g_wB[o1] = l;
}

// ============================================================================
// Kernel 1: proj = X @ W^T via 3x fp16 mma.sync m16n8k16 (Markidis split).
// CTA tile 128x128, BK=32, 8 warps (2m x 4n), 2 CTAs/SM, 3-stage cp.async.
// All operands pre-split + fragment-permuted in global (r9-validated, ~138us).
// ============================================================================
#define STAGE_B   32768
#define GEMM_SMEM (3 * STAGE_B)

__global__ __launch_bounds__(256, 2)
void fsnn_gemm_mma() {
    extern __shared__ char smem[];
    const uint32_t sm_u = smem_u32(smem);

    const int tid  = threadIdx.x;
    const int lane = tid & 31;
    const int wid  = tid >> 5;
    const int wm   = wid >> 2;
    const int wn   = wid & 3;
    const int mblk = blockIdx.x >> 2;
    const int nblk = blockIdx.x & 3;

    float acc[4][4][4];
#pragma unroll
    for (int i = 0; i < 4; i++)
#pragma unroll
        for (int j = 0; j < 4; j++)
#pragma unroll
            for (int q = 0; q < 4; q++) acc[i][j][q] = 0.0f;

    auto issueLoads = [&](int ch, int buf) {
        uint32_t dst = sm_u + buf * STAGE_B;
#pragma unroll
        for (int i = 0; i < 4; i++) {
            int id = tid + i * 256;
            int p = id >> 9, mt = (id >> 6) & 7, sx = (id >> 5) & 1, ln = id & 31;
            const __half* src = g_af +
                (((((size_t)p * 4000 + mblk * 8 + mt) * 16) + ch * 2 + sx) * 32 + ln) * 8;
            asm volatile("cp.async.cg.shared.global [%0], [%1], 16;"
                         :: "r"(dst + id * 16), "l"(src));
        }
        const __half* srcB = g_wB + (size_t)(nblk * 8 + ch) * 8192;
#pragma unroll
        for (int i = 0; i < 4; i++) {
            int id = tid + i * 256;
            asm volatile("cp.async.cg.shared.global [%0], [%1], 16;"
                         :: "r"(dst + 16384 + id * 16), "l"(srcB + id * 8));
        }
        asm volatile("cp.async.commit_group;");
    };

    auto compute = [&](int buf) {
        const char* bA = smem + buf * STAGE_B;
        const char* bB = bA + 16384;
#pragma unroll
        for (int s = 0; s < 2; s++) {
            uint32_t bf[2][4][2];
#pragma unroll
            for (int p = 0; p < 2; p++)
#pragma unroll
                for (int ntl = 0; ntl < 4; ntl++) {
                    int nt = wn * 4 + ntl;
                    uint2 v = *(const uint2*)(bB + (((p * 16 + nt) * 32 + lane) * 2 + s) * 8);
                    bf[p][ntl][0] = v.x;
                    bf[p][ntl][1] = v.y;
                }
#pragma unroll
            for (int mtl = 0; mtl < 4; mtl++) {
                int mt = wm * 4 + mtl;
                uint4 v0 = *(const uint4*)(bA + (((0 * 8 + mt) * 2 + s) * 32 + lane) * 16);
                uint4 v1 = *(const uint4*)(bA + (((1 * 8 + mt) * 2 + s) * 32 + lane) * 16);
                uint32_t a_h0[4] = {v0.x, v0.y, v0.z, v0.w};
                uint32_t a_h1[4] = {v1.x, v1.y, v1.z, v1.w};
#pragma unroll
                for (int ntl = 0; ntl < 4; ntl++) mma16(acc[mtl][ntl], a_h0, bf[0][ntl]);
#pragma unroll
                for (int ntl = 0; ntl < 4; ntl++) mma16(acc[mtl][ntl], a_h0, bf[1][ntl]);
#pragma unroll
                for (int ntl = 0; ntl < 4; ntl++) mma16(acc[mtl][ntl], a_h1, bf[0][ntl]);
            }
        }
    };

    issueLoads(0, 0);
    issueLoads(1, 1);
#pragma unroll
    for (int c = 0; c < 8; c++) {
        if (c == 7) asm volatile("cp.async.wait_group 0;" ::: "memory");
        else        asm volatile("cp.async.wait_group 1;" ::: "memory");
        __syncthreads();
        if (c + 2 < 8) issueLoads(c + 2, (c + 2) % 3);
        compute(c % 3);
    }

    const int m0 = mblk * 128;
    const int n0 = nblk * 128;
#pragma unroll
    for (int mtl = 0; mtl < 4; mtl++) {
#pragma unroll
        for (int ntl = 0; ntl < 4; ntl++) {
            int row = m0 + wm * 64 + mtl * 16 + (lane >> 2);
            int col = n0 + wn * 32 + ntl * 8 + (lane & 3) * 2;
            float* dst = g_proj + (size_t)row * NFILT + col;
            *(float2*)dst = make_float2(acc[mtl][ntl][0], acc[mtl][ntl][1]);
            *(float2*)(dst + (size_t)8 * NFILT) = make_float2(acc[mtl][ntl][2], acc[mtl][ntl][3]);
        }
    }
}

// ----------------------------------------------------------------------------
// Kernel 2: LIF scan via per-thread cp.async smem ring (DYNAMIC smem, 50 KB).
// 50-slot ring, 5 commit groups of 10 steps, wait_group 4 (max 5 pending)
// -> 40-step lookahead. No barriers. Fused decoder epilogue.
// ----------------------------------------------------------------------------
__global__ __launch_bounds__(256)
void fsnn_scan(const float* __restrict__ dec_w, float* __restrict__ out) {
    extern __shared__ float ss[];                 // RING * 256 floats (dynamic)
    const int tid  = threadIdx.x;
    const int idx  = blockIdx.x * 256 + tid;      // 0..65535 = b*512 + f
    const int lane = tid & 31;
    const int b = idx >> 9;
    const int f = idx & 511;
    const float* __restrict__ p = g_proj + idx;
    const uint32_t slot = smem_u32(ss) + tid * 4; // + ringoff

    // Prologue: 4 groups covering steps 0..39
#pragma unroll
    for (int gq = 0; gq < 4; gq++) {
#pragma unroll
        for (int j = 0; j < GRP; j++) {
            int t = gq * GRP + j;
            asm volatile("cp.async.ca.shared.global [%0], [%1], 4;"
                         :: "r"(slot + t * 1024), "l"(p + (size_t)t * NBF) : "memory");
        }
        asm volatile("cp.async.commit_group;" ::: "memory");
    }

    float u = 0.0f, tr = 0.0f, cnt = 0.0f;
    uint32_t ri = 40 * 1024;                      // ring offset for issue (step t+40)
    uint32_t rc = 0;                              // ring offset for consume (step t)
    const float* pg = p + (size_t)40 * NBF;       // issue address for step t+40

#pragma unroll 1
    for (int t = 0; t < TSTEPS; t += GRP) {       // 50 iterations
#pragma unroll
        for (int j = 0; j < GRP; j++) {
            asm volatile("cp.async.ca.shared.global [%0], [%1], 4;"
                         :: "r"(slot + ri + j * 1024), "l"(pg + (size_t)j * NBF) : "memory");
        }
        asm volatile("cp.async.commit_group;" ::: "memory");
        asm volatile("cp.async.wait_group 4;" ::: "memory");

#pragma unroll
        for (int j = 0; j < GRP; j++) {
            float x;
            asm volatile("ld.shared.f32 %0, [%1];" : "=f"(x) : "r"(slot + rc + j * 1024));
            tr = 0.95f * tr + x;
            u  = 0.9f  * u  + tr;
            if (u > 1.0f) { cnt += 1.0f; u = 0.0f; }
        }

        ri += GRP * 1024; if (ri == RING * 1024) ri = 0;
        rc += GRP * 1024; if (rc == RING * 1024) rc = 0;
        pg += (size_t)GRP * NBF;
    }
    asm volatile("cp.async.wait_all;" ::: "memory");

    // fused decoder
#pragma unroll
    for (int c = 0; c < NCLS; c++) {
        float v = cnt * dec_w[c * NFILT + f];
#pragma unroll
        for (int o = 16; o; o >>= 1) v += __shfl_xor_sync(0xFFFFFFFFu, v, o);
        if (lane == 0) atomicAdd(&out[b * NCLS + c], v);
    }
}

// ----------------------------------------------------------------------------
extern "C" void kernel_launch(void* const* d_in, const int* in_sizes, int n_in,
                              void* d_out, int out_size) {
    const float* x     = (const float*)d_in[0];   // [500,128,256]
    const float* w     = (const float*)d_in[1];   // [512,256]
    const float* dec_w = (const float*)d_in[2];   // [10,512]
    const float* dec_b = (const float*)d_in[3];   // [10]
    float* out = (float*)d_out;                   // [128,10]

    static bool attr_done = false;
    if (!attr_done) {
        cudaFuncSetAttribute(fsnn_gemm_mma, cudaFuncAttributeMaxDynamicSharedMemorySize, GEMM_SMEM);
        cudaFuncSetAttribute(fsnn_scan,     cudaFuncAttributeMaxDynamicSharedMemorySize, SCAN_SMEM);
        attr_done = true;
    }

    fsnn_asplit<<<2048000 / 256, 256>>>(x);       // 8000 blocks
    fsnn_wsplit<<<(NFILT * WIN + 255) / 256, 256>>>(w, dec_b, out);
    fsnn_gemm_mma<<<2000, 256, GEMM_SMEM>>>();
    fsnn_scan<<<NBF / 256, 256, SCAN_SMEM>>>(dec_w, out);
}

// round 16
// speedup vs baseline: 1.0449x; 1.0449x over previous
#include <cuda_runtime.h>
#include <cuda_fp16.h>
#include <cstdint>

// Problem constants
#define TSTEPS 500
#define BATCH  128
#define WIN    256
#define NFILT  512
#define NCLS   10
#define MROWS  (TSTEPS * BATCH)   // 64000
#define NBF    (BATCH * NFILT)    // 65536

// Scan config: 4 trajectories/thread, 16B cp.async per step
#define SBLK   64                 // threads per scan block
#define SGRP   4                  // steps per commit group
#define SRING  24                 // ring slots (steps) = 6 groups

// Scratch (device globals: no runtime allocation allowed).
// g_proj padded: scan prefetches up to step t+23 past the end.
__device__ __align__(16) float g_proj[(size_t)(TSTEPS + 32) * NBF];     // 136 MB
// A in full mma-fragment layout: [p(2)][rt(4000)][ks(16)][lane(32)] x 8 halves
__device__ __align__(16) __half g_af[(size_t)2 * 4000 * 16 * 32 * 8];   // 65.5 MB
// W in full mma-fragment layout: [nblk(4)][ch(8)] x 8192 halves,
// inner: [p(2)][nt(16)][lane(32)][s(2)][reg(2)][slot(2)]
__device__ __align__(16) __half g_wB[4 * 8 * 8192];                     // 512 KB

// ============================================================================
// helpers
// ============================================================================
__device__ __forceinline__ uint32_t smem_u32(const void* p) {
    uint32_t a;
    asm("{ .reg .u64 t; cvta.to.shared.u64 t, %1; cvt.u32.u64 %0, t; }" : "=r"(a) : "l"(p));
    return a;
}
__device__ __forceinline__ void mma16(float* c, const uint32_t* a, const uint32_t* b) {
    asm volatile(
        "mma.sync.aligned.m16n8k16.row.col.f32.f16.f16.f32 "
        "{%0,%1,%2,%3}, {%4,%5,%6,%7}, {%8,%9}, {%0,%1,%2,%3};"
        : "+f"(c[0]), "+f"(c[1]), "+f"(c[2]), "+f"(c[3])
        : "r"(a[0]), "r"(a[1]), "r"(a[2]), "r"(a[3]), "r"(b[0]), "r"(b[1]));
}
__device__ __forceinline__ void split2h(float x, __half& h0, __half& h1) {
    h0 = __float2half_rn(x);
    h1 = __float2half_rn(x - __half2float(h0));
}

// ============================================================================
// Kernel 0a: split X -> 2 fp16 planes directly in mma-fragment layout.
// ============================================================================
__global__ __launch_bounds__(256)
void fsnn_asplit(const float* __restrict__ X) {
    int idx  = blockIdx.x * 256 + threadIdx.x;   // 0 .. 2,048,000-1
    int lane = idx & 31;
    int ks   = (idx >> 5) & 15;
    int rt   = idx >> 9;
    int rl = lane >> 2, g = lane & 3;
    int rlo = rt * 16 + rl, rhi = rlo + 8;
    int k0 = ks * 16 + 2 * g;

    float2 lo_a = *(const float2*)(X + (size_t)rlo * WIN + k0);
    float2 lo_b = *(const float2*)(X + (size_t)rlo * WIN + k0 + 8);
    float2 hi_a = *(const float2*)(X + (size_t)rhi * WIN + k0);
    float2 hi_b = *(const float2*)(X + (size_t)rhi * WIN + k0 + 8);

    __half h[8], l[8];
    split2h(lo_a.x, h[0], l[0]); split2h(lo_a.y, h[1], l[1]);
    split2h(hi_a.x, h[2], l[2]); split2h(hi_a.y, h[3], l[3]);
    split2h(lo_b.x, h[4], l[4]); split2h(lo_b.y, h[5], l[5]);
    split2h(hi_b.x, h[6], l[6]); split2h(hi_b.y, h[7], l[7]);

    size_t o0 = ((((size_t)0 * 4000 + rt) * 16 + ks) * 32 + lane) * 8;
    size_t o1 = ((((size_t)1 * 4000 + rt) * 16 + ks) * 32 + lane) * 8;
    __half2* d0 = (__half2*)(g_af + o0);
    __half2* d1 = (__half2*)(g_af + o1);
#pragma unroll
    for (int j = 0; j < 4; j++) {
        d0[j] = __halves2half2(h[2 * j], h[2 * j + 1]);
        d1[j] = __halves2half2(l[2 * j], l[2 * j + 1]);
    }
}

// ============================================================================
// Kernel 0b: split W -> 2 fp16 planes (fragment layout) + init out with bias
// ============================================================================
__global__ __launch_bounds__(256)
void fsnn_wsplit(const float* __restrict__ Wm, const float* __restrict__ dec_b,
                 float* __restrict__ out) {
    if (blockIdx.x == 0) {
        for (int j = threadIdx.x; j < BATCH * NCLS; j += 256)
            out[j] = dec_b[j % NCLS];
    }
    int i = blockIdx.x * blockDim.x + threadIdx.x;
    if (i >= NFILT * WIN) return;
    int n = i >> 8, k = i & 255;
    __half h, l;
    split2h(Wm[i], h, l);

    int nblk = n >> 7, nn = n & 127, nt = nn >> 3;
    int ch = k >> 5, kk = k & 31;
    int s = kk >> 4, q = kk & 15;
    int reg = q >> 3, kr = q & 7;
    int lane = (nn & 7) * 4 + (kr >> 1);
    int slot = kr & 1;

    size_t chbase = (size_t)(nblk * 8 + ch) * 8192;
    size_t o0 = chbase + ((((size_t)(0 * 16 + nt) * 32 + lane) * 2 + s) * 4) + reg * 2 + slot;
    size_t o1 = chbase + ((((size_t)(1 * 16 + nt) * 32 + lane) * 2 + s) * 4) + reg * 2 + slot;
    g_wB[o0] = h;
    g_wB[o1] = l;
}

// ============================================================================
// Kernel 1: proj = X @ W^T via 3x fp16 mma.sync m16n8k16 (Markidis split).
// CTA tile 128x128, BK=32, 8 warps, 2 CTAs/SM, 3-stage cp.async (r9-validated)
// ============================================================================
#define STAGE_B   32768
#define GEMM_SMEM (3 * STAGE_B)

__global__ __launch_bounds__(256, 2)
void fsnn_gemm_mma() {
    extern __shared__ char smem[];
    const uint32_t sm_u = smem_u32(smem);

    const int tid  = threadIdx.x;
    const int lane = tid & 31;
    const int wid  = tid >> 5;
    const int wm   = wid >> 2;
    const int wn   = wid & 3;
    const int mblk = blockIdx.x >> 2;
    const int nblk = blockIdx.x & 3;

    float acc[4][4][4];
#pragma unroll
    for (int i = 0; i < 4; i++)
#pragma unroll
        for (int j = 0; j < 4; j++)
#pragma unroll
            for (int q = 0; q < 4; q++) acc[i][j][q] = 0.0f;

    auto issueLoads = [&](int ch, int buf) {
        uint32_t dst = sm_u + buf * STAGE_B;
#pragma unroll
        for (int i = 0; i < 4; i++) {
            int id = tid + i * 256;
            int p = id >> 9, mt = (id >> 6) & 7, sx = (id >> 5) & 1, ln = id & 31;
            const __half* src = g_af +
                (((((size_t)p * 4000 + mblk * 8 + mt) * 16) + ch * 2 + sx) * 32 + ln) * 8;
            asm volatile("cp.async.cg.shared.global [%0], [%1], 16;"
                         :: "r"(dst + id * 16), "l"(src));
        }
        const __half* srcB = g_wB + (size_t)(nblk * 8 + ch) * 8192;
#pragma unroll
        for (int i = 0; i < 4; i++) {
            int id = tid + i * 256;
            asm volatile("cp.async.cg.shared.global [%0], [%1], 16;"
                         :: "r"(dst + 16384 + id * 16), "l"(srcB + id * 8));
        }
        asm volatile("cp.async.commit_group;");
    };

    auto compute = [&](int buf) {
        const char* bA = smem + buf * STAGE_B;
        const char* bB = bA + 16384;
#pragma unroll
        for (int s = 0; s < 2; s++) {
            uint32_t bf[2][4][2];
#pragma unroll
            for (int p = 0; p < 2; p++)
#pragma unroll
                for (int ntl = 0; ntl < 4; ntl++) {
                    int nt = wn * 4 + ntl;
                    uint2 v = *(const uint2*)(bB + (((p * 16 + nt) * 32 + lane) * 2 + s) * 8);
                    bf[p][ntl][0] = v.x;
                    bf[p][ntl][1] = v.y;
                }
#pragma unroll
            for (int mtl = 0; mtl < 4; mtl++) {
                int mt = wm * 4 + mtl;
                uint4 v0 = *(const uint4*)(bA + (((0 * 8 + mt) * 2 + s) * 32 + lane) * 16);
                uint4 v1 = *(const uint4*)(bA + (((1 * 8 + mt) * 2 + s) * 32 + lane) * 16);
                uint32_t a_h0[4] = {v0.x, v0.y, v0.z, v0.w};
                uint32_t a_h1[4] = {v1.x, v1.y, v1.z, v1.w};
#pragma unroll
                for (int ntl = 0; ntl < 4; ntl++) mma16(acc[mtl][ntl], a_h0, bf[0][ntl]);
#pragma unroll
                for (int ntl = 0; ntl < 4; ntl++) mma16(acc[mtl][ntl], a_h0, bf[1][ntl]);
#pragma unroll
                for (int ntl = 0; ntl < 4; ntl++) mma16(acc[mtl][ntl], a_h1, bf[0][ntl]);
            }
        }
    };

    issueLoads(0, 0);
    issueLoads(1, 1);
#pragma unroll
    for (int c = 0; c < 8; c++) {
        if (c == 7) asm volatile("cp.async.wait_group 0;" ::: "memory");
        else        asm volatile("cp.async.wait_group 1;" ::: "memory");
        __syncthreads();
        if (c + 2 < 8) issueLoads(c + 2, (c + 2) % 3);
        compute(c % 3);
    }

    const int m0 = mblk * 128;
    const int n0 = nblk * 128;
#pragma unroll
    for (int mtl = 0; mtl < 4; mtl++) {
#pragma unroll
        for (int ntl = 0; ntl < 4; ntl++) {
            int row = m0 + wm * 64 + mtl * 16 + (lane >> 2);
            int col = n0 + wn * 32 + ntl * 8 + (lane & 3) * 2;
            float* dst = g_proj + (size_t)row * NFILT + col;
            *(float2*)dst = make_float2(acc[mtl][ntl][0], acc[mtl][ntl][1]);
            *(float2*)(dst + (size_t)8 * NFILT) = make_float2(acc[mtl][ntl][2], acc[mtl][ntl][3]);
        }
    }
}

// ----------------------------------------------------------------------------
// Kernel 2: LIF scan, 4 trajectories per thread (f..f+3), 16B cp.async/step.
// 16384 threads = 256 blocks x 64. Ring: 24 steps x 1KB = 24KB static smem,
// 6 groups of 4 steps, wait_group 5 -> 20-step lookahead (5.2MB in flight).
// No barriers (threads touch only their own slots). Fused decoder epilogue.
// ----------------------------------------------------------------------------
__global__ __launch_bounds__(SBLK)
void fsnn_scan(const float* __restrict__ dec_w, float* __restrict__ out) {
    __shared__ float ss[SRING * SBLK * 4];        // 24 KB
    const int tid  = threadIdx.x;
    const int gid  = blockIdx.x * SBLK + tid;     // 0..16383
    const int lane = tid & 31;
    const int b  = gid >> 7;                      // 128 threads per batch row
    const int f4 = (gid & 127) * 4;               // base filter index
    const float* __restrict__ p = g_proj + (size_t)b * NFILT + f4;
    const uint32_t slot = smem_u32(ss) + tid * 16;   // + step*1024

    // Prologue: 5 groups covering steps 0..19
#pragma unroll
    for (int gq = 0; gq < 5; gq++) {
#pragma unroll
        for (int j = 0; j < SGRP; j++) {
            int t = gq * SGRP + j;
            asm volatile("cp.async.cg.shared.global [%0], [%1], 16;"
                         :: "r"(slot + t * (SBLK * 16)), "l"(p + (size_t)t * NBF) : "memory");
        }
        asm volatile("cp.async.commit_group;" ::: "memory");
    }

    float u0 = 0.f, u1 = 0.f, u2 = 0.f, u3 = 0.f;
    float t0 = 0.f, t1 = 0.f, t2 = 0.f, t3 = 0.f;
    float c0 = 0.f, c1 = 0.f, c2 = 0.f, c3 = 0.f;

    uint32_t ri = 20 * (SBLK * 16);               // ring offset: issue (step t+20)
    uint32_t rc = 0;                              // ring offset: consume (step t)
    const float* pg = p + (size_t)20 * NBF;

#pragma unroll 1
    for (int t = 0; t < TSTEPS; t += SGRP) {      // 125 iterations
        // Issue group for steps t+20..t+23 (pad covers the tail)
#pragma unroll
        for (int j = 0; j < SGRP; j++) {
            asm volatile("cp.async.cg.shared.global [%0], [%1], 16;"
                         :: "r"(slot + ri + j * (SBLK * 16)), "l"(pg + (size_t)j * NBF) : "memory");
        }
        asm volatile("cp.async.commit_group;" ::: "memory");
        // 6 pending; wait_group 5 -> group [t..t+3] complete
        asm volatile("cp.async.wait_group 5;" ::: "memory");

#pragma unroll
        for (int j = 0; j < SGRP; j++) {
            float x0, x1, x2, x3;
            asm volatile("ld.shared.v4.f32 {%0,%1,%2,%3}, [%4];"
                         : "=f"(x0), "=f"(x1), "=f"(x2), "=f"(x3)
                         : "r"(slot + rc + j * (SBLK * 16)));
            t0 = 0.95f * t0 + x0; u0 = 0.9f * u0 + t0;
            if (u0 > 1.0f) { c0 += 1.0f; u0 = 0.0f; }
            t1 = 0.95f * t1 + x1; u1 = 0.9f * u1 + t1;
            if (u1 > 1.0f) { c1 += 1.0f; u1 = 0.0f; }
            t2 = 0.95f * t2 + x2; u2 = 0.9f * u2 + t2;
            if (u2 > 1.0f) { c2 += 1.0f; u2 = 0.0f; }
            t3 = 0.95f * t3 + x3; u3 = 0.9f * u3 + t3;
            if (u3 > 1.0f) { c3 += 1.0f; u3 = 0.0f; }
        }

        ri += SGRP * (SBLK * 16); if (ri == SRING * (SBLK * 16)) ri = 0;
        rc += SGRP * (SBLK * 16); if (rc == SRING * (SBLK * 16)) rc = 0;
        pg += (size_t)SGRP * NBF;
    }
    asm volatile("cp.async.wait_all;" ::: "memory");   // drain before exit

    // Fused decoder: warp covers 128 consecutive f for one b.
#pragma unroll
    for (int c = 0; c < NCLS; c++) {
        float4 w4 = *(const float4*)(dec_w + c * NFILT + f4);
        float v = c0 * w4.x + c1 * w4.y + c2 * w4.z + c3 * w4.w;
#pragma unroll
        for (int o = 16; o; o >>= 1) v += __shfl_xor_sync(0xFFFFFFFFu, v, o);
        if (lane == 0) atomicAdd(&out[b * NCLS + c], v);
    }
}

// ----------------------------------------------------------------------------
extern "C" void kernel_launch(void* const* d_in, const int* in_sizes, int n_in,
                              void* d_out, int out_size) {
    const float* x     = (const float*)d_in[0];   // [500,128,256]
    const float* w     = (const float*)d_in[1];   // [512,256]
    const float* dec_w = (const float*)d_in[2];   // [10,512]
    const float* dec_b = (const float*)d_in[3];   // [10]
    float* out = (float*)d_out;                   // [128,10]

    static bool attr_done = false;
    if (!attr_done) {
        cudaFuncSetAttribute(fsnn_gemm_mma, cudaFuncAttributeMaxDynamicSharedMemorySize, GEMM_SMEM);
        attr_done = true;
    }

    fsnn_asplit<<<2048000 / 256, 256>>>(x);       // 8000 blocks
    fsnn_wsplit<<<(NFILT * WIN + 255) / 256, 256>>>(w, dec_b, out);
    fsnn_gemm_mma<<<2000, 256, GEMM_SMEM>>>();
    fsnn_scan<<<16384 / SBLK, SBLK>>>(dec_w, out);
}

// round 17
// speedup vs baseline: 1.2223x; 1.1698x over previous
#include <cuda_runtime.h>
#include <cuda_fp16.h>
#include <cstdint>

// Problem constants
#define TSTEPS 500
#define BATCH  128
#define WIN    256
#define NFILT  512
#define NCLS   10
#define MROWS  (TSTEPS * BATCH)   // 64000
#define NBF    (BATCH * NFILT)    // 65536

// Scan config: 4 trajectories/thread, 16B cp.async per step
#define SBLK   64                 // threads per scan block
#define SGRP   4                  // steps per commit group
#define SRING  40                 // ring slots (steps) = 10 groups
#define SLOOK  36                 // lookahead steps (9 groups in flight)

// Scratch (device globals: no runtime allocation allowed).
// g_proj padded: scan prefetches up to step t+39 past the end.
__device__ __align__(16) float g_proj[(size_t)(TSTEPS + 64) * NBF];     // 148 MB
// A in full mma-fragment layout: [p(2)][rt(4000)][ks(16)][lane(32)] x 8 halves
__device__ __align__(16) __half g_af[(size_t)2 * 4000 * 16 * 32 * 8];   // 65.5 MB
// W in full mma-fragment layout: [nblk(4)][ch(8)] x 8192 halves,
// inner: [p(2)][nt(16)][lane(32)][s(2)][reg(2)][slot(2)]
__device__ __align__(16) __half g_wB[4 * 8 * 8192];                     // 512 KB

// ============================================================================
// helpers
// ============================================================================
__device__ __forceinline__ uint32_t smem_u32(const void* p) {
    uint32_t a;
    asm("{ .reg .u64 t; cvta.to.shared.u64 t, %1; cvt.u32.u64 %0, t; }" : "=r"(a) : "l"(p));
    return a;
}
__device__ __forceinline__ void mma16(float* c, const uint32_t* a, const uint32_t* b) {
    asm volatile(
        "mma.sync.aligned.m16n8k16.row.col.f32.f16.f16.f32 "
        "{%0,%1,%2,%3}, {%4,%5,%6,%7}, {%8,%9}, {%0,%1,%2,%3};"
        : "+f"(c[0]), "+f"(c[1]), "+f"(c[2]), "+f"(c[3])
        : "r"(a[0]), "r"(a[1]), "r"(a[2]), "r"(a[3]), "r"(b[0]), "r"(b[1]));
}
__device__ __forceinline__ void split2h(float x, __half& h0, __half& h1) {
    h0 = __float2half_rn(x);
    h1 = __float2half_rn(x - __half2float(h0));
}

// ============================================================================
// Kernel 0: MERGED prep. Blocks 0..7999: split X -> fragment-layout fp16
// planes. Blocks 8000..8511: split W -> fragment planes (+ bias init).
// ============================================================================
#define ABLOCKS 8000
#define WBLOCKS 512

__global__ __launch_bounds__(256)
void fsnn_prep(const float* __restrict__ X, const float* __restrict__ Wm,
               const float* __restrict__ dec_b, float* __restrict__ out) {
    if (blockIdx.x < ABLOCKS) {
        // ---- A split (identical to r9 asplit) ----
        int idx  = blockIdx.x * 256 + threadIdx.x;   // 0 .. 2,048,000-1
        int lane = idx & 31;
        int ks   = (idx >> 5) & 15;
        int rt   = idx >> 9;
        int rl = lane >> 2, g = lane & 3;
        int rlo = rt * 16 + rl, rhi = rlo + 8;
        int k0 = ks * 16 + 2 * g;

        float2 lo_a = *(const float2*)(X + (size_t)rlo * WIN + k0);
        float2 lo_b = *(const float2*)(X + (size_t)rlo * WIN + k0 + 8);
        float2 hi_a = *(const float2*)(X + (size_t)rhi * WIN + k0);
        float2 hi_b = *(const float2*)(X + (size_t)rhi * WIN + k0 + 8);

        __half h[8], l[8];
        split2h(lo_a.x, h[0], l[0]); split2h(lo_a.y, h[1], l[1]);
        split2h(hi_a.x, h[2], l[2]); split2h(hi_a.y, h[3], l[3]);
        split2h(lo_b.x, h[4], l[4]); split2h(lo_b.y, h[5], l[5]);
        split2h(hi_b.x, h[6], l[6]); split2h(hi_b.y, h[7], l[7]);

        size_t o0 = ((((size_t)0 * 4000 + rt) * 16 + ks) * 32 + lane) * 8;
        size_t o1 = ((((size_t)1 * 4000 + rt) * 16 + ks) * 32 + lane) * 8;
        __half2* d0 = (__half2*)(g_af + o0);
        __half2* d1 = (__half2*)(g_af + o1);
#pragma unroll
        for (int j = 0; j < 4; j++) {
            d0[j] = __halves2half2(h[2 * j], h[2 * j + 1]);
            d1[j] = __halves2half2(l[2 * j], l[2 * j + 1]);
        }
    } else {
        // ---- W split (identical to r9 wsplit) ----
        if (blockIdx.x == ABLOCKS) {
            for (int j = threadIdx.x; j < BATCH * NCLS; j += 256)
                out[j] = dec_b[j % NCLS];
        }
        int i = (blockIdx.x - ABLOCKS) * 256 + threadIdx.x;
        if (i >= NFILT * WIN) return;
        int n = i >> 8, k = i & 255;
        __half h, l;
        split2h(Wm[i], h, l);

        int nblk = n >> 7, nn = n & 127, nt = nn >> 3;
        int ch = k >> 5, kk = k & 31;
        int s = kk >> 4, q = kk & 15;
        int reg = q >> 3, kr = q & 7;
        int lane = (nn & 7) * 4 + (kr >> 1);
        int slot = kr & 1;

        size_t chbase = (size_t)(nblk * 8 + ch) * 8192;
        size_t o0 = chbase + ((((size_t)(0 * 16 + nt) * 32 + lane) * 2 + s) * 4) + reg * 2 + slot;
        size_t o1 = chbase + ((((size_t)(1 * 16 + nt) * 32 + lane) * 2 + s) * 4) + reg * 2 + slot;
        g_wB[o0] = h;
        g_wB[o1] = l;
    }
}

// ============================================================================
// Kernel 1: proj = X @ W^T via 3x fp16 mma.sync m16n8k16 (Markidis split).
// CTA tile 128x128, BK=32, 8 warps, 2 CTAs/SM, 3-stage cp.async (r9-validated)
// ============================================================================
#define STAGE_B   32768
#define GEMM_SMEM (3 * STAGE_B)

__global__ __launch_bounds__(256, 2)
void fsnn_gemm_mma() {
    extern __shared__ char smem[];
    const uint32_t sm_u = smem_u32(smem);

    const int tid  = threadIdx.x;
    const int lane = tid & 31;
    const int wid  = tid >> 5;
    const int wm   = wid >> 2;
    const int wn   = wid & 3;
    const int mblk = blockIdx.x >> 2;
    const int nblk = blockIdx.x & 3;

    float acc[4][4][4];
#pragma unroll
    for (int i = 0; i < 4; i++)
#pragma unroll
        for (int j = 0; j < 4; j++)
#pragma unroll
            for (int q = 0; q < 4; q++) acc[i][j][q] = 0.0f;

    auto issueLoads = [&](int ch, int buf) {
        uint32_t dst = sm_u + buf * STAGE_B;
#pragma unroll
        for (int i = 0; i < 4; i++) {
            int id = tid + i * 256;
            int p = id >> 9, mt = (id >> 6) & 7, sx = (id >> 5) & 1, ln = id & 31;
            const __half* src = g_af +
                (((((size_t)p * 4000 + mblk * 8 + mt) * 16) + ch * 2 + sx) * 32 + ln) * 8;
            asm volatile("cp.async.cg.shared.global [%0], [%1], 16;"
                         :: "r"(dst + id * 16), "l"(src));
        }
        const __half* srcB = g_wB + (size_t)(nblk * 8 + ch) * 8192;
#pragma unroll
        for (int i = 0; i < 4; i++) {
            int id = tid + i * 256;
            asm volatile("cp.async.cg.shared.global [%0], [%1], 16;"
                         :: "r"(dst + 16384 + id * 16), "l"(srcB + id * 8));
        }
        asm volatile("cp.async.commit_group;");
    };

    auto compute = [&](int buf) {
        const char* bA = smem + buf * STAGE_B;
        const char* bB = bA + 16384;
#pragma unroll
        for (int s = 0; s < 2; s++) {
            uint32_t bf[2][4][2];
#pragma unroll
            for (int p = 0; p < 2; p++)
#pragma unroll
                for (int ntl = 0; ntl < 4; ntl++) {
                    int nt = wn * 4 + ntl;
                    uint2 v = *(const uint2*)(bB + (((p * 16 + nt) * 32 + lane) * 2 + s) * 8);
                    bf[p][ntl][0] = v.x;
                    bf[p][ntl][1] = v.y;
                }
#pragma unroll
            for (int mtl = 0; mtl < 4; mtl++) {
                int mt = wm * 4 + mtl;
                uint4 v0 = *(const uint4*)(bA + (((0 * 8 + mt) * 2 + s) * 32 + lane) * 16);
                uint4 v1 = *(const uint4*)(bA + (((1 * 8 + mt) * 2 + s) * 32 + lane) * 16);
                uint32_t a_h0[4] = {v0.x, v0.y, v0.z, v0.w};
                uint32_t a_h1[4] = {v1.x, v1.y, v1.z, v1.w};
#pragma unroll
                for (int ntl = 0; ntl < 4; ntl++) mma16(acc[mtl][ntl], a_h0, bf[0][ntl]);
#pragma unroll
                for (int ntl = 0; ntl < 4; ntl++) mma16(acc[mtl][ntl], a_h0, bf[1][ntl]);
#pragma unroll
                for (int ntl = 0; ntl < 4; ntl++) mma16(acc[mtl][ntl], a_h1, bf[0][ntl]);
            }
        }
    };

    issueLoads(0, 0);
    issueLoads(1, 1);
#pragma unroll
    for (int c = 0; c < 8; c++) {
        if (c == 7) asm volatile("cp.async.wait_group 0;" ::: "memory");
        else        asm volatile("cp.async.wait_group 1;" ::: "memory");
        __syncthreads();
        if (c + 2 < 8) issueLoads(c + 2, (c + 2) % 3);
        compute(c % 3);
    }

    const int m0 = mblk * 128;
    const int n0 = nblk * 128;
#pragma unroll
    for (int mtl = 0; mtl < 4; mtl++) {
#pragma unroll
        for (int ntl = 0; ntl < 4; ntl++) {
            int row = m0 + wm * 64 + mtl * 16 + (lane >> 2);
            int col = n0 + wn * 32 + ntl * 8 + (lane & 3) * 2;
            float* dst = g_proj + (size_t)row * NFILT + col;
            *(float2*)dst = make_float2(acc[mtl][ntl][0], acc[mtl][ntl][1]);
            *(float2*)(dst + (size_t)8 * NFILT) = make_float2(acc[mtl][ntl][2], acc[mtl][ntl][3]);
        }
    }
}

// ----------------------------------------------------------------------------
// Kernel 2: LIF scan, 4 trajectories per thread (f..f+3), 16B cp.async/step.
// 16384 threads = 256 blocks x 64. Ring: 40 steps x 1KB = 40KB static smem,
// 10 groups of 4 steps, wait_group 9 -> 36-step lookahead (9.4MB in flight).
// No barriers (threads touch only their own slots). Fused decoder epilogue.
// ----------------------------------------------------------------------------
__global__ __launch_bounds__(SBLK)
void fsnn_scan(const float* __restrict__ dec_w, float* __restrict__ out) {
    __shared__ float ss[SRING * SBLK * 4];        // 40 KB
    const int tid  = threadIdx.x;
    const int gid  = blockIdx.x * SBLK + tid;     // 0..16383
    const int lane = tid & 31;
    const int b  = gid >> 7;                      // 128 threads per batch row
    const int f4 = (gid & 127) * 4;               // base filter index
    const float* __restrict__ p = g_proj + (size_t)b * NFILT + f4;
    const uint32_t slot = smem_u32(ss) + tid * 16;   // + step*(SBLK*16)

    // Prologue: 9 groups covering steps 0..35
#pragma unroll
    for (int gq = 0; gq < SLOOK / SGRP; gq++) {
#pragma unroll
        for (int j = 0; j < SGRP; j++) {
            int t = gq * SGRP + j;
            asm volatile("cp.async.cg.shared.global [%0], [%1], 16;"
                         :: "r"(slot + t * (SBLK * 16)), "l"(p + (size_t)t * NBF) : "memory");
        }
        asm volatile("cp.async.commit_group;" ::: "memory");
    }

    float u0 = 0.f, u1 = 0.f, u2 = 0.f, u3 = 0.f;
    float t0 = 0.f, t1 = 0.f, t2 = 0.f, t3 = 0.f;
    float c0 = 0.f, c1 = 0.f, c2 = 0.f, c3 = 0.f;

    uint32_t ri = SLOOK * (SBLK * 16);            // ring offset: issue (step t+36)
    uint32_t rc = 0;                              // ring offset: consume (step t)
    const float* pg = p + (size_t)SLOOK * NBF;

#pragma unroll 1
    for (int t = 0; t < TSTEPS; t += SGRP) {      // 125 iterations
        // Issue group for steps t+36..t+39 (pad covers the tail)
#pragma unroll
        for (int j = 0; j < SGRP; j++) {
            asm volatile("cp.async.cg.shared.global [%0], [%1], 16;"
                         :: "r"(slot + ri + j * (SBLK * 16)), "l"(pg + (size_t)j * NBF) : "memory");
        }
        asm volatile("cp.async.commit_group;" ::: "memory");
        // 10 pending; wait_group 9 -> group [t..t+3] complete
        asm volatile("cp.async.wait_group 9;" ::: "memory");

#pragma unroll
        for (int j = 0; j < SGRP; j++) {
            float x0, x1, x2, x3;
            asm volatile("ld.shared.v4.f32 {%0,%1,%2,%3}, [%4];"
                         : "=f"(x0), "=f"(x1), "=f"(x2), "=f"(x3)
                         : "r"(slot + rc + j * (SBLK * 16)));
            t0 = 0.95f * t0 + x0; u0 = 0.9f * u0 + t0;
            if (u0 > 1.0f) { c0 += 1.0f; u0 = 0.0f; }
            t1 = 0.95f * t1 + x1; u1 = 0.9f * u1 + t1;
            if (u1 > 1.0f) { c1 += 1.0f; u1 = 0.0f; }
            t2 = 0.95f * t2 + x2; u2 = 0.9f * u2 + t2;
            if (u2 > 1.0f) { c2 += 1.0f; u2 = 0.0f; }
            t3 = 0.95f * t3 + x3; u3 = 0.9f * u3 + t3;
            if (u3 > 1.0f) { c3 += 1.0f; u3 = 0.0f; }
        }

        ri += SGRP * (SBLK * 16); if (ri == SRING * (SBLK * 16)) ri = 0;
        rc += SGRP * (SBLK * 16); if (rc == SRING * (SBLK * 16)) rc = 0;
        pg += (size_t)SGRP * NBF;
    }
    asm volatile("cp.async.wait_all;" ::: "memory");   // drain before exit

    // Fused decoder: warp covers 128 consecutive f for one b.
#pragma unroll
    for (int c = 0; c < NCLS; c++) {
        float4 w4 = *(const float4*)(dec_w + c * NFILT + f4);
        float v = c0 * w4.x + c1 * w4.y + c2 * w4.z + c3 * w4.w;
#pragma unroll
        for (int o = 16; o; o >>= 1) v += __shfl_xor_sync(0xFFFFFFFFu, v, o);
        if (lane == 0) atomicAdd(&out[b * NCLS + c], v);
    }
}

// ----------------------------------------------------------------------------
extern "C" void kernel_launch(void* const* d_in, const int* in_sizes, int n_in,
                              void* d_out, int out_size) {
    const float* x     = (const float*)d_in[0];   // [500,128,256]
    const float* w     = (const float*)d_in[1];   // [512,256]
    const float* dec_w = (const float*)d_in[2];   // [10,512]
    const float* dec_b = (const float*)d_in[3];   // [10]
    float* out = (float*)d_out;                   // [128,10]

    static bool attr_done = false;
    if (!attr_done) {
        cudaFuncSetAttribute(fsnn_gemm_mma, cudaFuncAttributeMaxDynamicSharedMemorySize, GEMM_SMEM);
        attr_done = true;
    }

    fsnn_prep<<<ABLOCKS + WBLOCKS, 256>>>(x, w, dec_b, out);
    fsnn_gemm_mma<<<2000, 256, GEMM_SMEM>>>();
    fsnn_scan<<<16384 / SBLK, SBLK>>>(dec_w, out);
}